// round 5
// baseline (speedup 1.0000x reference)
#include <cuda_runtime.h>
#include <cuda_fp16.h>
#include <cstdint>

// Problem constants
#define B_   8
#define N_   2048
#define F0_  128
#define HID_ 64
#define OUT_ 16
#define K_   10

#define GRID 128
#define TPB  256

// ---------------- device scratch (static; no allocation) ----------------
__device__ __half2 g_Lh[N_ * N_ / 2];        // 8 MB fp16 L, row-major (w-pairs)
__device__ float g_z[2][N_];                 // ping-pong (I-L^T)^k 1 chain
__device__ float g_r[2][N_];                 // ping-pong Horner accumulator
__device__ float g_a[K_ + 1];                // a_i = theta_i * C(K,i)
__device__ float g_Hf[B_ * N_ * HID_];       // relu(X@W1+b1), 4 MB
__device__ float g_part[B_][16][HID_];       // per-(b,chunk) weighted partials
__device__ unsigned g_barcnt = 0;            // monotonic ticket counter
__device__ unsigned g_barrel = 0;            // monotonic release generation

__constant__ float c_binom[K_ + 1] = {1.f, 10.f, 45.f, 120.f, 210.f, 252.f,
                                      210.f, 120.f, 45.f, 10.f, 1.f};

#define BARN(id, cnt) asm volatile("bar.sync %0, %1;" :: "r"(id), "r"(cnt) : "memory")

// Grid barrier: call from exactly ONE thread per block. Monotonic counters are
// consistent across graph replays (ticket/release advance in lockstep).
__device__ __forceinline__ void grid_arrive_wait() {
    __threadfence();
    unsigned ticket = atomicAdd(&g_barcnt, 1u) + 1u;
    unsigned gen = (ticket + GRID - 1u) / GRID;
    if ((ticket & (GRID - 1u)) == 0u) {
        atomicAdd(&g_barrel, 1u);
    }
    while (*((volatile unsigned*)&g_barrel) < gen) {
        __nanosleep(64);
    }
    __threadfence();
}

__global__ __launch_bounds__(TPB, 1) void mega_kernel(
    const float* __restrict__ X,  const float* __restrict__ L,
    const float* __restrict__ W1, const float* __restrict__ b1,
    const float* __restrict__ W2, const float* __restrict__ b2,
    const float* __restrict__ theta, float* __restrict__ out)
{
    __shared__ float w1s[F0_ * HID_];   // 32 KB (hf half)
    __shared__ float b1s[HID_];
    __shared__ float red[4][16][8];     // filter block-reduce (az0,az1,ar0,ar1)
    __shared__ float redc[4][HID_];     // phase-C block-reduce
    __shared__ float hgsh[B_ * HID_];   // final Hg (block 0)

    const int tid = threadIdx.x;
    const int bid = blockIdx.x;

    if (tid < 128) {
        // ======================= FILTER HALF (threads 0-127) ==============
        const int ft = tid;

        // ---- Phase A: convert L fp32 -> fp16 (+ setup by block 0) -------
        {
            const float4* L4 = (const float4*)L;
            for (int i = bid * 128 + ft; i < N_ * N_ / 4; i += GRID * 128) {
                float4 f = L4[i];
                g_Lh[2 * i]     = __floats2half2_rn(f.x, f.y);
                g_Lh[2 * i + 1] = __floats2half2_rn(f.z, f.w);
            }
        }
        if (bid == 0) {
            float tK = theta[K_];
            for (int i = ft; i < N_; i += 128) { g_z[0][i] = 1.0f; g_r[0][i] = tK; }
            if (ft <= K_) g_a[ft] = theta[ft] * c_binom[ft];
        }
        BARN(1, 128);
        if (ft == 0) grid_arrive_wait();
        BARN(1, 128);

        // ---- Phase B: 10 fused Bernstein/Horner passes -------------------
        const int tx = ft & 7;            // 0..7  : half2 column lane
        const int ty = ft >> 3;           // 0..15 : v group
        const int w2 = bid * 8 + tx;      // owns w = 2*w2, 2*w2+1
        const __half2* Lp = g_Lh + w2;    // column slice: L1-resident across passes

        for (int j = 1; j <= K_; ++j) {
            const int pin = (j - 1) & 1;
            const float* zp = g_z[pin];
            const float* rp = g_r[pin];

            float az0 = 0.f, az1 = 0.f, ar0 = 0.f, ar1 = 0.f;
#pragma unroll 16
            for (int v = ty; v < N_; v += 16) {
                float2 f = __half22float2(Lp[v * (N_ / 2)]);
                float zc = __ldcg(zp + v);       // L2-coherent (rewritten by other SMs)
                float rc = __ldcg(rp + v);
                az0 += f.x * zc;  az1 += f.y * zc;
                ar0 += f.x * rc;  ar1 += f.y * rc;
            }
            red[0][ty][tx] = az0;  red[1][ty][tx] = az1;
            red[2][ty][tx] = ar0;  red[3][ty][tx] = ar1;
            BARN(1, 128);

            if (ft < 16) {
                const int c = ft & 7;         // tx lane
                const int e = ft >> 3;        // 0 = even w, 1 = odd w
                float sz = 0.f, sr = 0.f;
#pragma unroll
                for (int g = 0; g < 16; ++g) {
                    sz += red[e][g][c];
                    sr += red[2 + e][g][c];
                }
                const int w = bid * 16 + 2 * c + e;
                float zold = __ldcg(&g_z[pin][w]);
                float znew = zold - sz;
                float rnew = sr + g_a[K_ - j] * znew;
                g_z[pin ^ 1][w] = znew;
                g_r[pin ^ 1][w] = rnew;
            }
            BARN(1, 128);
            if (ft == 0) grid_arrive_wait();
            BARN(1, 128);
        }
        // final v = g_r[0] (pass 10 writes parity 0)
    } else {
        // ======================= HF HALF (threads 128-255) ================
        const int ht = tid - 128;

        for (int i = ht; i < F0_ * HID_; i += 128) w1s[i] = W1[i];
        if (ht < HID_) b1s[ht] = b1[ht];
        BARN(2, 128);

        const int row = bid * 128 + ht;                 // 0..16383 = (b,n)
        const float* xr = X + (size_t)row * F0_;

        float acc[HID_];
#pragma unroll
        for (int h = 0; h < HID_; ++h) acc[h] = b1s[h];

        for (int f0 = 0; f0 < F0_; f0 += 16) {
            float4 xv[4];
#pragma unroll
            for (int i = 0; i < 4; ++i)
                xv[i] = reinterpret_cast<const float4*>(xr + f0)[i];
            const float* xf = reinterpret_cast<const float*>(xv);
#pragma unroll
            for (int i = 0; i < 16; ++i) {
                float x = xf[i];
                const float4* wrow =
                    reinterpret_cast<const float4*>(&w1s[(f0 + i) * HID_]);
#pragma unroll
                for (int q = 0; q < 16; ++q) {
                    float4 wv = wrow[q];
                    acc[q * 4 + 0] += x * wv.x;
                    acc[q * 4 + 1] += x * wv.y;
                    acc[q * 4 + 2] += x * wv.z;
                    acc[q * 4 + 3] += x * wv.w;
                }
            }
        }
        float4* hout = reinterpret_cast<float4*>(g_Hf + (size_t)row * HID_);
#pragma unroll
        for (int q = 0; q < 16; ++q) {
            float4 v;
            v.x = fmaxf(acc[q * 4 + 0], 0.f);
            v.y = fmaxf(acc[q * 4 + 1], 0.f);
            v.z = fmaxf(acc[q * 4 + 2], 0.f);
            v.w = fmaxf(acc[q * 4 + 3], 0.f);
            hout[q] = v;
        }
    }

    // =================== join: filter done AND hf done ====================
    __syncthreads();
    if (tid == 0) grid_arrive_wait();
    __syncthreads();

    // =================== Phase C: Hg partials = v^T Hf / N ================
    {
        const int b = bid >> 4;           // 0..7
        const int chunk = bid & 15;       // 0..15 (128 rows each)
        const int h = tid & 63;
        const int nsub = tid >> 6;        // 0..3
        const int nbase = chunk * 128 + nsub * 32;

        float accc = 0.f;
#pragma unroll 8
        for (int i = 0; i < 32; ++i) {
            const int n = nbase + i;
            float vn = __ldcg(&g_r[0][n]);
            accc += vn * g_Hf[((size_t)(b * N_ + n)) * HID_ + h];
        }
        redc[nsub][h] = accc;
        __syncthreads();
        if (tid < HID_) {
            float s = (redc[0][tid] + redc[1][tid]) +
                      (redc[2][tid] + redc[3][tid]);
            g_part[b][chunk][tid] = s * (1.0f / (float)N_);
        }
    }
    __syncthreads();
    if (tid == 0) grid_arrive_wait();
    __syncthreads();

    // =================== Final: logits (block 0 only) =====================
    if (bid == 0) {
        for (int t = tid; t < B_ * HID_; t += TPB) {
            int bb = t >> 6, hh = t & 63;
            float s = 0.f;
#pragma unroll
            for (int c = 0; c < 16; ++c) s += g_part[bb][c][hh];
            hgsh[t] = s;
        }
        __syncthreads();
        if (tid < B_ * OUT_) {
            int bb = tid >> 4, o = tid & 15;
            float accf = b2[o];
#pragma unroll
            for (int hh = 0; hh < HID_; ++hh)
                accf += hgsh[bb * HID_ + hh] * W2[hh * OUT_ + o];
            out[bb * OUT_ + o] = accf;
        }
    }
}

// ---------------- launcher ----------------------------------------------
extern "C" void kernel_launch(void* const* d_in, const int* in_sizes, int n_in,
                              void* d_out, int out_size) {
    const float* X     = (const float*)d_in[0];
    const float* L     = (const float*)d_in[1];
    const float* W1    = (const float*)d_in[2];
    const float* b1    = (const float*)d_in[3];
    const float* W2    = (const float*)d_in[4];
    const float* b2    = (const float*)d_in[5];
    const float* theta = (const float*)d_in[6];
    float* out = (float*)d_out;

    mega_kernel<<<GRID, TPB>>>(X, L, W1, b1, W2, b2, theta, out);
}

// round 6
// speedup vs baseline: 1.0772x; 1.0772x over previous
#include <cuda_runtime.h>
#include <cuda_fp16.h>
#include <cstdint>

// Problem constants
#define B_   8
#define N_   2048
#define F0_  128
#define HID_ 64
#define OUT_ 16
#define K_   10

#define VCHUNKS 32          // 64 rows per chunk
#define ROWS_PER_CHUNK (N_ / VCHUNKS)

// ---------------- device scratch (static; no allocation) ----------------
__device__ __half2 g_Lh[N_ * N_ / 2];     // 8 MB fp16 copy of L (row-major, w pairs)
__device__ float g_z[2][N_];              // ping-pong (I-L^T)^k 1 chain
__device__ float g_r[2][N_];              // ping-pong Horner accumulator
__device__ float g_a[K_ + 1];             // a_i = theta_i * C(K,i)
__device__ float g_pzT[N_][VCHUNKS];      // TRANSPOSED partials: [w][chunk]
__device__ float g_prT[N_][VCHUNKS];
__device__ float g_part[B_][32][HID_];    // per-(b,chunk) partial Hg sums

__constant__ float c_binom[K_ + 1] = {1.f, 10.f, 45.f, 120.f, 210.f, 252.f,
                                      210.f, 120.f, 45.f, 10.f, 1.f};

// ---------------- setup: init z0 = 1, r0 = a_K * 1, coefficients --------
__global__ void setup_kernel(const float* __restrict__ theta) {
    int i = blockIdx.x * 1024 + threadIdx.x;
    if (i < N_) {
        g_z[0][i] = 1.0f;
        g_r[0][i] = theta[K_];   // a_K = theta_K * C(K,K)
    }
    if (i < K_ + 1) g_a[i] = theta[i] * c_binom[i];
}

// ---------------- convert L (fp32) -> g_Lh (fp16 pairs) -----------------
__global__ void convert_kernel(const float* __restrict__ L) {
    int idx = blockIdx.x * 256 + threadIdx.x;       // over N*N/4
    float4 f = reinterpret_cast<const float4*>(L)[idx];
    g_Lh[2 * idx]     = __floats2half2_rn(f.x, f.y);
    g_Lh[2 * idx + 1] = __floats2half2_rn(f.z, f.w);
}

// ---------------- pass phase 1: partial column dots ----------------------
// grid (8 wtiles, 32 vchunks), block 128. Each thread: 2 adjacent w (half2),
// 64 rows fully unrolled -> 64 outstanding coalesced loads.
__global__ __launch_bounds__(128) void pass_partial(int pin) {
    __shared__ float szc[ROWS_PER_CHUNK];
    __shared__ float src[ROWS_PER_CHUNK];

    int tx = threadIdx.x;                 // 0..127
    int v0 = blockIdx.y * ROWS_PER_CHUNK;

    if (tx < ROWS_PER_CHUNK) szc[tx] = g_z[pin][v0 + tx];
    else if (tx < 2 * ROWS_PER_CHUNK) src[tx - ROWS_PER_CHUNK] = g_r[pin][v0 + tx - ROWS_PER_CHUNK];
    __syncthreads();

    int w2 = blockIdx.x * 128 + tx;       // half2 column index (w = 2*w2, 2*w2+1)
    const __half2* Lp = g_Lh + (size_t)v0 * (N_ / 2) + w2;

    float az0 = 0.f, az1 = 0.f, ar0 = 0.f, ar1 = 0.f;
#pragma unroll
    for (int v = 0; v < ROWS_PER_CHUNK; ++v) {
        float2 f = __half22float2(Lp[(size_t)v * (N_ / 2)]);
        float zc = szc[v], rc = src[v];
        az0 += f.x * zc;  az1 += f.y * zc;
        ar0 += f.x * rc;  ar1 += f.y * rc;
    }
    int c = blockIdx.y;
    g_pzT[2 * w2][c]     = az0;
    g_pzT[2 * w2 + 1][c] = az1;
    g_prT[2 * w2][c]     = ar0;
    g_prT[2 * w2 + 1][c] = ar1;
}

// ---------------- pass phase 2: reduce partials, update z/r --------------
// grid 16 x 128 threads. Thread w reads its 32 partials as 8 contiguous
// float4 per array (fully coalesced, MLP=16). Fixed order -> deterministic.
__global__ __launch_bounds__(128) void pass_reduce(int pin, int coefIdx) {
    int w = blockIdx.x * 128 + threadIdx.x;

    const float4* pz = reinterpret_cast<const float4*>(g_pzT[w]);
    const float4* pr = reinterpret_cast<const float4*>(g_prT[w]);

    float4 zq[8], rq[8];
#pragma unroll
    for (int i = 0; i < 8; ++i) zq[i] = pz[i];
#pragma unroll
    for (int i = 0; i < 8; ++i) rq[i] = pr[i];

    float sz = 0.f, sr = 0.f;
#pragma unroll
    for (int i = 0; i < 8; ++i) {
        sz += (zq[i].x + zq[i].y) + (zq[i].z + zq[i].w);
        sr += (rq[i].x + rq[i].y) + (rq[i].z + rq[i].w);
    }
    float znew = g_z[pin][w] - sz;
    float rnew = sr + g_a[coefIdx] * znew;
    g_z[pin ^ 1][w] = znew;
    g_r[pin ^ 1][w] = rnew;
}

// ---------------- fused Hf = relu(X@W1+b1), weighted partial reduce -----
__global__ void hf_kernel(const float* __restrict__ X,
                          const float* __restrict__ W1,
                          const float* __restrict__ b1) {
    __shared__ float w1s[F0_ * HID_];   // 32 KB
    __shared__ float b1s[HID_];
    __shared__ float red[4][32];

    int tx = threadIdx.x;               // 0..63
    int ty = threadIdx.y;               // 0..1
    int tid = ty * 64 + tx;

    for (int i = tid; i < F0_ * HID_; i += 128) w1s[i] = W1[i];
    if (tid < HID_) b1s[tid] = b1[tid];
    __syncthreads();

    int b = blockIdx.y;
    int chunk = blockIdx.x;
    int n = chunk * 64 + tx;
    const float* xr = X + ((size_t)b * N_ + n) * F0_;
    int h0 = ty * 32;

    float acc[32];
#pragma unroll
    for (int h = 0; h < 32; ++h) acc[h] = b1s[h0 + h];

    for (int f0 = 0; f0 < F0_; f0 += 16) {
        float4 xv[4];
#pragma unroll
        for (int i = 0; i < 4; ++i)
            xv[i] = reinterpret_cast<const float4*>(xr + f0)[i];
        const float* xf = reinterpret_cast<const float*>(xv);
#pragma unroll
        for (int i = 0; i < 16; ++i) {
            float x = xf[i];
            const float4* wrow =
                reinterpret_cast<const float4*>(&w1s[(f0 + i) * HID_ + h0]);
#pragma unroll
            for (int q = 0; q < 8; ++q) {
                float4 wv = wrow[q];
                acc[q * 4 + 0] += x * wv.x;
                acc[q * 4 + 1] += x * wv.y;
                acc[q * 4 + 2] += x * wv.z;
                acc[q * 4 + 3] += x * wv.w;
            }
        }
    }

    float s = g_r[0][n] * (1.0f / (float)N_);   // v[n] / N
#pragma unroll
    for (int h = 0; h < 32; ++h) acc[h] = fmaxf(acc[h], 0.f) * s;

#pragma unroll
    for (int h = 0; h < 32; ++h) {
        float v_ = acc[h];
        v_ += __shfl_xor_sync(0xffffffffu, v_, 16);
        v_ += __shfl_xor_sync(0xffffffffu, v_, 8);
        v_ += __shfl_xor_sync(0xffffffffu, v_, 4);
        v_ += __shfl_xor_sync(0xffffffffu, v_, 2);
        v_ += __shfl_xor_sync(0xffffffffu, v_, 1);
        acc[h] = v_;
    }
    int lane = tid & 31, warp = tid >> 5;
    if (lane == 0) {
#pragma unroll
        for (int h = 0; h < 32; ++h) red[warp][h] = acc[h];
    }
    __syncthreads();
    if (tid < 64) {
        int hh = tid & 31;
        int grp = tid >> 5;
        g_part[b][chunk][grp * 32 + hh] = red[grp * 2][hh] + red[grp * 2 + 1][hh];
    }
}

// ---------------- final: reduce chunks, logits = Hg@W2 + b2 -------------
__global__ void final_kernel(const float* __restrict__ W2,
                             const float* __restrict__ b2,
                             float* __restrict__ out) {
    __shared__ float hg[B_ * HID_];
    int t = threadIdx.x;                 // 512 threads = (b,h) pairs
    int b = t >> 6, h = t & 63;
    float s = 0.f;
#pragma unroll
    for (int c = 0; c < 32; ++c) s += g_part[b][c][h];
    hg[t] = s;
    __syncthreads();
    if (t < B_ * OUT_) {
        int bb = t >> 4, o = t & 15;
        float acc = b2[o];
#pragma unroll
        for (int hh = 0; hh < HID_; ++hh)
            acc += hg[bb * HID_ + hh] * W2[hh * OUT_ + o];
        out[bb * OUT_ + o] = acc;
    }
}

// ---------------- launcher ----------------------------------------------
extern "C" void kernel_launch(void* const* d_in, const int* in_sizes, int n_in,
                              void* d_out, int out_size) {
    const float* X     = (const float*)d_in[0];
    const float* L     = (const float*)d_in[1];
    const float* W1    = (const float*)d_in[2];
    const float* b1    = (const float*)d_in[3];
    const float* W2    = (const float*)d_in[4];
    const float* b2    = (const float*)d_in[5];
    const float* theta = (const float*)d_in[6];
    float* out = (float*)d_out;

    setup_kernel<<<2, 1024>>>(theta);
    convert_kernel<<<(N_ * N_ / 4) / 256, 256>>>(L);

    // 10 fused filter passes: pass j consumes parity (j-1)&1, coef a[K-j]
    for (int j = 1; j <= K_; ++j) {
        pass_partial<<<dim3(8, VCHUNKS), 128>>>((j - 1) & 1);
        pass_reduce<<<N_ / 128, 128>>>((j - 1) & 1, K_ - j);
    }
    // final r lands in parity 0

    hf_kernel<<<dim3(32, B_), dim3(64, 2)>>>(X, W1, b1);
    final_kernel<<<1, 512>>>(W2, b2, out);
}